// round 4
// baseline (speedup 1.0000x reference)
#include <cuda_runtime.h>
#include <cuda_bf16.h>
#include <cstdint>
#include <math.h>

#define SEQ 4096
#define EMB 1280
#define NH 16
#define HD 80
#define QKSCALE 8.94427190999915878564f  // sqrt(80) — reference MULTIPLIES by sqrt(head_dim)

// ---------------- device scratch (no allocations allowed) ----------------
__device__ float g_q[NH * SEQ * HD];
__device__ float g_k[NH * SEQ * HD];
__device__ float g_v[NH * SEQ * HD];
__device__ __align__(16) __nv_bfloat16 g_ah[SEQ * EMB];       // A hi (hidden / attn out)
__device__ __align__(16) __nv_bfloat16 g_al[SEQ * EMB];       // A lo
__device__ __align__(16) __nv_bfloat16 g_bh[3 * EMB * EMB];   // B hi (w_qkv / w_proj)
__device__ __align__(16) __nv_bfloat16 g_bl[3 * EMB * EMB];   // B lo

// ---------------- mma.sync + cp.async helpers (compute_103-safe) ----------------
__device__ __forceinline__ void mma_bf16(float* d, const uint32_t* a, const uint32_t* b) {
    asm volatile(
        "mma.sync.aligned.m16n8k16.row.col.f32.bf16.bf16.f32 "
        "{%0,%1,%2,%3}, {%4,%5,%6,%7}, {%8,%9}, {%0,%1,%2,%3};\n"
        : "+f"(d[0]), "+f"(d[1]), "+f"(d[2]), "+f"(d[3])
        : "r"(a[0]), "r"(a[1]), "r"(a[2]), "r"(a[3]), "r"(b[0]), "r"(b[1]));
}
__device__ __forceinline__ uint32_t smem_u32(const void* p) {
    uint32_t a;
    asm("{ .reg .u64 t; cvta.to.shared.u64 t, %1; cvt.u32.u64 %0, t; }" : "=r"(a) : "l"(p));
    return a;
}
__device__ __forceinline__ void cp_async16(uint32_t s, const void* g) {
    asm volatile("cp.async.cg.shared.global [%0], [%1], 16;\n" :: "r"(s), "l"(g));
}
#define CP_COMMIT() asm volatile("cp.async.commit_group;\n" ::: "memory")
#define CP_WAIT1()  asm volatile("cp.async.wait_group 1;\n" ::: "memory")

__device__ __forceinline__ uint32_t bf2(float x, float y) {
    __nv_bfloat162 v = __floats2bfloat162_rn(x, y);
    return *reinterpret_cast<uint32_t*>(&v);
}
__device__ __forceinline__ float bflo(float x) {   // residual after bf16 round
    return x - __bfloat162float(__float2bfloat16(x));
}

// ---------------- fp32 -> bf16 hi/lo split ----------------
__global__ void split_kernel(const float* __restrict__ x,
                             __nv_bfloat16* __restrict__ hi,
                             __nv_bfloat16* __restrict__ lo, int n4)
{
    int i = blockIdx.x * 256 + threadIdx.x;
    if (i >= n4) return;
    float4 v = reinterpret_cast<const float4*>(x)[i];
    __nv_bfloat16 h0 = __float2bfloat16(v.x);
    __nv_bfloat16 h1 = __float2bfloat16(v.y);
    __nv_bfloat16 h2 = __float2bfloat16(v.z);
    __nv_bfloat16 h3 = __float2bfloat16(v.w);
    __nv_bfloat162* hp = reinterpret_cast<__nv_bfloat162*>(hi);
    __nv_bfloat162* lp = reinterpret_cast<__nv_bfloat162*>(lo);
    hp[2 * i]     = __nv_bfloat162{h0, h1};
    hp[2 * i + 1] = __nv_bfloat162{h2, h3};
    lp[2 * i]     = __nv_bfloat162{__float2bfloat16(v.x - __bfloat162float(h0)),
                                   __float2bfloat16(v.y - __bfloat162float(h1))};
    lp[2 * i + 1] = __nv_bfloat162{__float2bfloat16(v.z - __bfloat162float(h2)),
                                   __float2bfloat16(v.w - __bfloat162float(h3))};
}

// ---------------- HMMA split-bf16 GEMM: C[M,N] = A*B^T + bias ----------------
#define GPAD   40
#define TILE_B (128 * GPAD * 2)
#define BUF_B  (4 * TILE_B)
#define GEMM_SMEM (2 * BUF_B)

__global__ __launch_bounds__(256, 2) void gemm_tc_kernel(
    const __nv_bfloat16* __restrict__ Ah, const __nv_bfloat16* __restrict__ Al,
    const __nv_bfloat16* __restrict__ Bh, const __nv_bfloat16* __restrict__ Bl,
    const float* __restrict__ bias, float* __restrict__ C, int K, int mode)
{
    extern __shared__ char smem[];
    uint32_t sb = smem_u32(smem);

    int t = threadIdx.x, lane = t & 31, wid = t >> 5;
    int wm = wid >> 2, wn = wid & 3;
    int c0 = blockIdx.x * 128, r0 = blockIdx.y * 128;

    const __nv_bfloat16* src[4] = {Ah + (size_t)r0 * K, Al + (size_t)r0 * K,
                                   Bh + (size_t)c0 * K, Bl + (size_t)c0 * K};

    auto load_chunk = [&](int p, int k0) {
        #pragma unroll
        for (int m = 0; m < 4; m++) {
            #pragma unroll
            for (int i = 0; i < 2; i++) {
                int e = t + i * 256;
                int row = e >> 2, col = e & 3;
                cp_async16(sb + p * BUF_B + m * TILE_B + row * (GPAD * 2) + col * 16,
                           src[m] + (size_t)row * K + k0 + col * 8);
            }
        }
    };

    float acc[4][4][4];
    #pragma unroll
    for (int a = 0; a < 4; a++)
        #pragma unroll
        for (int b = 0; b < 4; b++)
            #pragma unroll
            for (int c = 0; c < 4; c++) acc[a][b][c] = 0.f;

    int r = lane >> 2, cq = lane & 3;
    int nch = K / 32;

    load_chunk(0, 0);
    CP_COMMIT();

    for (int c = 0; c < nch; c++) {
        int p = c & 1;
        if (c + 1 < nch) load_chunk(1 - p, (c + 1) * 32);
        CP_COMMIT();
        CP_WAIT1();
        __syncthreads();

        const char* buf = smem + p * BUF_B;
        const char* tAh = buf;
        const char* tAl = buf + TILE_B;
        const char* tBh = buf + 2 * TILE_B;
        const char* tBl = buf + 3 * TILE_B;

        #pragma unroll
        for (int ks = 0; ks < 32; ks += 16) {
            int kb = (ks + cq * 2) * 2;
            uint32_t ah[4][4], bh[4][2];
            #pragma unroll
            for (int mf = 0; mf < 4; mf++) {
                int row0 = wm * 64 + mf * 16 + r;
                ah[mf][0] = *(const uint32_t*)(tAh + row0 * 80 + kb);
                ah[mf][1] = *(const uint32_t*)(tAh + (row0 + 8) * 80 + kb);
                ah[mf][2] = *(const uint32_t*)(tAh + row0 * 80 + kb + 16);
                ah[mf][3] = *(const uint32_t*)(tAh + (row0 + 8) * 80 + kb + 16);
            }
            #pragma unroll
            for (int nf = 0; nf < 4; nf++) {
                int n0 = wn * 32 + nf * 8 + r;
                bh[nf][0] = *(const uint32_t*)(tBh + n0 * 80 + kb);
                bh[nf][1] = *(const uint32_t*)(tBh + n0 * 80 + kb + 16);
            }
            #pragma unroll
            for (int mf = 0; mf < 4; mf++)
                #pragma unroll
                for (int nf = 0; nf < 4; nf++)
                    mma_bf16(acc[mf][nf], ah[mf], bh[nf]);

            uint32_t bl[4][2];
            #pragma unroll
            for (int nf = 0; nf < 4; nf++) {
                int n0 = wn * 32 + nf * 8 + r;
                bl[nf][0] = *(const uint32_t*)(tBl + n0 * 80 + kb);
                bl[nf][1] = *(const uint32_t*)(tBl + n0 * 80 + kb + 16);
            }
            #pragma unroll
            for (int mf = 0; mf < 4; mf++)
                #pragma unroll
                for (int nf = 0; nf < 4; nf++)
                    mma_bf16(acc[mf][nf], ah[mf], bl[nf]);

            uint32_t al[4][4];
            #pragma unroll
            for (int mf = 0; mf < 4; mf++) {
                int row0 = wm * 64 + mf * 16 + r;
                al[mf][0] = *(const uint32_t*)(tAl + row0 * 80 + kb);
                al[mf][1] = *(const uint32_t*)(tAl + (row0 + 8) * 80 + kb);
                al[mf][2] = *(const uint32_t*)(tAl + row0 * 80 + kb + 16);
                al[mf][3] = *(const uint32_t*)(tAl + (row0 + 8) * 80 + kb + 16);
            }
            #pragma unroll
            for (int mf = 0; mf < 4; mf++)
                #pragma unroll
                for (int nf = 0; nf < 4; nf++)
                    mma_bf16(acc[mf][nf], al[mf], bh[nf]);
        }
        __syncthreads();
    }

    #pragma unroll
    for (int mf = 0; mf < 4; mf++) {
        #pragma unroll
        for (int nf = 0; nf < 4; nf++) {
            #pragma unroll
            for (int half = 0; half < 2; half++) {
                int row = r0 + wm * 64 + mf * 16 + r + half * 8;
                int col = c0 + wn * 32 + nf * 8 + cq * 2;
                float v0 = acc[mf][nf][half * 2 + 0] + bias[col];
                float v1 = acc[mf][nf][half * 2 + 1] + bias[col + 1];
                if (mode == 0) {
                    #pragma unroll
                    for (int j = 0; j < 2; j++) {
                        int cc = col + j;
                        float v = j ? v1 : v0;
                        int which = cc / EMB;
                        int rem = cc - which * EMB;
                        int h = rem / HD, dd = rem - h * HD;
                        float* dst = (which == 0) ? g_q : (which == 1) ? g_k : g_v;
                        dst[((size_t)h * SEQ + row) * HD + dd] = v;
                    }
                } else {
                    float2* dst = (float2*)(C + (size_t)row * EMB + col);
                    *dst = make_float2(v0, v1);
                }
            }
        }
    }
}

// ---------------- RoPE in place on g_q, g_k ----------------
__global__ void rope_kernel(const float* __restrict__ cosb,
                            const float* __restrict__ sinb)
{
    int idx = blockIdx.x * blockDim.x + threadIdx.x;
    if (idx >= NH * SEQ * (HD / 2)) return;
    int d = idx % 40;
    int s = (idx / 40) % SEQ;
    int h = idx / (40 * SEQ);
    float c1 = cosb[s * HD + d],      s1 = sinb[s * HD + d];
    float c2 = cosb[s * HD + d + 40], s2 = sinb[s * HD + d + 40];
    size_t base = ((size_t)h * SEQ + s) * HD;
    float q1 = g_q[base + d], q2 = g_q[base + d + 40];
    g_q[base + d]      = q1 * c1 - q2 * s1;
    g_q[base + d + 40] = q2 * c2 + q1 * s2;
    float k1 = g_k[base + d], k2 = g_k[base + d + 40];
    g_k[base + d]      = k1 * c1 - k2 * s1;
    g_k[base + d + 40] = k2 * c2 + k1 * s2;
}

// ---------------- Flash attention, HMMA split-bf16 ----------------
// CTA: 64 q-rows x 1 head, 128 threads (4 warps, warp = 16 rows).
// K tile smem [64][KROW] hi/lo; V tile smem transposed [80][VROW] hi/lo.
#define KROW 88
#define VROW 72
#define FLASH_SMEM ((64 * KROW * 2 + 80 * VROW * 2) * 2)   // 45568 B

__global__ __launch_bounds__(128) void flash_kernel(const int* __restrict__ cu, int ncu)
{
    extern __shared__ __nv_bfloat16 fsm[];
    __nv_bfloat16* Kh = fsm;
    __nv_bfloat16* Kl = Kh + 64 * KROW;
    __nv_bfloat16* Vh = Kl + 64 * KROW;
    __nv_bfloat16* Vl = Vh + 80 * VROW;

    int t = threadIdx.x, lane = t & 31, wid = t >> 5;
    int r = lane >> 2, cq = lane & 3;
    int h = blockIdx.y, qr0 = blockIdx.x * 64;

    // ---- Q fragments (hi/lo) in registers, pre-scaled ----
    uint32_t qh[5][4], ql[5][4];
    {
        const float* gq = g_q + ((size_t)h * SEQ + qr0 + wid * 16) * HD;
        #pragma unroll
        for (int ks = 0; ks < 5; ks++) {
            #pragma unroll
            for (int idx = 0; idx < 4; idx++) {
                int row = r + (idx & 1) * 8;
                int k = ks * 16 + 2 * cq + (idx >> 1) * 8;
                float2 v = *(const float2*)(gq + row * HD + k);
                v.x *= QKSCALE; v.y *= QKSCALE;
                qh[ks][idx] = bf2(v.x, v.y);
                ql[ks][idx] = bf2(bflo(v.x), bflo(v.y));
            }
        }
    }

    int s0 = 0, s1 = SEQ;
    for (int i = 0; i < ncu - 1; i++) {
        if (cu[i] <= qr0 && qr0 < cu[i + 1]) { s0 = cu[i]; s1 = cu[i + 1]; break; }
    }

    float o[10][4];
    #pragma unroll
    for (int nf = 0; nf < 10; nf++)
        #pragma unroll
        for (int j = 0; j < 4; j++) o[nf][j] = 0.f;
    float m0 = -INFINITY, m1 = -INFINITY, l0 = 0.f, l1 = 0.f;

    const float* gkb = g_k + (size_t)h * SEQ * HD;
    const float* gvb = g_v + (size_t)h * SEQ * HD;

    for (int kt = s0; kt < s1; kt += 64) {
        // ---- load K (row-major) and V (transposed) hi/lo into smem ----
        const float* gk = gkb + (size_t)kt * HD;
        const float* gv = gvb + (size_t)kt * HD;
        #pragma unroll
        for (int i = 0; i < 20; i++) {
            int e = t + i * 128;                 // float2 index, 2560 total
            int tok = e / 40, d2 = e % 40;
            float2 kv = *(const float2*)(gk + tok * HD + d2 * 2);
            *(__nv_bfloat162*)(&Kh[tok * KROW + d2 * 2]) =
                __floats2bfloat162_rn(kv.x, kv.y);
            *(__nv_bfloat162*)(&Kl[tok * KROW + d2 * 2]) =
                __floats2bfloat162_rn(bflo(kv.x), bflo(kv.y));
            float2 vv = *(const float2*)(gv + tok * HD + d2 * 2);
            int d = d2 * 2;
            Vh[d * VROW + tok]       = __float2bfloat16(vv.x);
            Vh[(d + 1) * VROW + tok] = __float2bfloat16(vv.y);
            Vl[d * VROW + tok]       = __float2bfloat16(bflo(vv.x));
            Vl[(d + 1) * VROW + tok] = __float2bfloat16(bflo(vv.y));
        }
        __syncthreads();

        // ---- S = Q K^T (3-term split) ----
        float s[8][4];
        #pragma unroll
        for (int nf = 0; nf < 8; nf++)
            #pragma unroll
            for (int j = 0; j < 4; j++) s[nf][j] = 0.f;

        #pragma unroll
        for (int ks = 0; ks < 5; ks++) {
            uint32_t bh[8][2], bl[8][2];
            #pragma unroll
            for (int nf = 0; nf < 8; nf++) {
                int n0 = (nf * 8 + r) * KROW + ks * 16 + 2 * cq;
                bh[nf][0] = *(const uint32_t*)&Kh[n0];
                bh[nf][1] = *(const uint32_t*)&Kh[n0 + 8];
                bl[nf][0] = *(const uint32_t*)&Kl[n0];
                bl[nf][1] = *(const uint32_t*)&Kl[n0 + 8];
            }
            #pragma unroll
            for (int nf = 0; nf < 8; nf++) mma_bf16(s[nf], qh[ks], bh[nf]);
            #pragma unroll
            for (int nf = 0; nf < 8; nf++) mma_bf16(s[nf], qh[ks], bl[nf]);
            #pragma unroll
            for (int nf = 0; nf < 8; nf++) mma_bf16(s[nf], ql[ks], bh[nf]);
        }

        // ---- online softmax (rows r and r+8, spread over quad) ----
        float mx0 = -INFINITY, mx1 = -INFINITY;
        #pragma unroll
        for (int nf = 0; nf < 8; nf++) {
            mx0 = fmaxf(mx0, fmaxf(s[nf][0], s[nf][1]));
            mx1 = fmaxf(mx1, fmaxf(s[nf][2], s[nf][3]));
        }
        mx0 = fmaxf(mx0, __shfl_xor_sync(0xffffffffu, mx0, 1));
        mx0 = fmaxf(mx0, __shfl_xor_sync(0xffffffffu, mx0, 2));
        mx1 = fmaxf(mx1, __shfl_xor_sync(0xffffffffu, mx1, 1));
        mx1 = fmaxf(mx1, __shfl_xor_sync(0xffffffffu, mx1, 2));
        float mn0 = fmaxf(m0, mx0), mn1 = fmaxf(m1, mx1);
        float c0 = __expf(m0 - mn0), c1 = __expf(m1 - mn1);
        float sum0 = 0.f, sum1 = 0.f;
        #pragma unroll
        for (int nf = 0; nf < 8; nf++) {
            s[nf][0] = __expf(s[nf][0] - mn0); sum0 += s[nf][0];
            s[nf][1] = __expf(s[nf][1] - mn0); sum0 += s[nf][1];
            s[nf][2] = __expf(s[nf][2] - mn1); sum1 += s[nf][2];
            s[nf][3] = __expf(s[nf][3] - mn1); sum1 += s[nf][3];
        }
        sum0 += __shfl_xor_sync(0xffffffffu, sum0, 1);
        sum0 += __shfl_xor_sync(0xffffffffu, sum0, 2);
        sum1 += __shfl_xor_sync(0xffffffffu, sum1, 1);
        sum1 += __shfl_xor_sync(0xffffffffu, sum1, 2);
        l0 = l0 * c0 + sum0; l1 = l1 * c1 + sum1;
        m0 = mn0; m1 = mn1;
        #pragma unroll
        for (int nf = 0; nf < 10; nf++) {
            o[nf][0] *= c0; o[nf][1] *= c0;
            o[nf][2] *= c1; o[nf][3] *= c1;
        }

        // ---- pack P into A-operand fragments (hi/lo) ----
        uint32_t ph[4][4], pl[4][4];
        #pragma unroll
        for (int kf = 0; kf < 4; kf++) {
            float* j0 = s[2 * kf];
            float* j1 = s[2 * kf + 1];
            ph[kf][0] = bf2(j0[0], j0[1]); pl[kf][0] = bf2(bflo(j0[0]), bflo(j0[1]));
            ph[kf][1] = bf2(j0[2], j0[3]); pl[kf][1] = bf2(bflo(j0[2]), bflo(j0[3]));
            ph[kf][2] = bf2(j1[0], j1[1]); pl[kf][2] = bf2(bflo(j1[0]), bflo(j1[1]));
            ph[kf][3] = bf2(j1[2], j1[3]); pl[kf][3] = bf2(bflo(j1[2]), bflo(j1[3]));
        }

        // ---- O += P V (3-term split) ----
        #pragma unroll
        for (int kf = 0; kf < 4; kf++) {
            uint32_t vh[10][2], vl[10][2];
            #pragma unroll
            for (int nf = 0; nf < 10; nf++) {
                int n0 = (nf * 8 + r) * VROW + kf * 16 + 2 * cq;
                vh[nf][0] = *(const uint32_t*)&Vh[n0];
                vh[nf][1] = *(const uint32_t*)&Vh[n0 + 8];
                vl[nf][0] = *(const uint32_t*)&Vl[n0];
                vl[nf][1] = *(const uint32_t*)&Vl[n0 + 8];
            }
            #pragma unroll
            for (int nf = 0; nf < 10; nf++) mma_bf16(o[nf], ph[kf], vh[nf]);
            #pragma unroll
            for (int nf = 0; nf < 10; nf++) mma_bf16(o[nf], ph[kf], vl[nf]);
            #pragma unroll
            for (int nf = 0; nf < 10; nf++) mma_bf16(o[nf], pl[kf], vh[nf]);
        }
        __syncthreads();
    }

    // ---- epilogue: normalize, split hi/lo, write to g_ah/g_al ----
    float inv0 = 1.f / l0, inv1 = 1.f / l1;
    int row0 = qr0 + wid * 16 + r;
    #pragma unroll
    for (int nf = 0; nf < 10; nf++) {
        int col = h * HD + nf * 8 + 2 * cq;
        float a0 = o[nf][0] * inv0, a1 = o[nf][1] * inv0;
        float b0 = o[nf][2] * inv1, b1 = o[nf][3] * inv1;
        *(__nv_bfloat162*)(&g_ah[(size_t)row0 * EMB + col]) = __floats2bfloat162_rn(a0, a1);
        *(__nv_bfloat162*)(&g_al[(size_t)row0 * EMB + col]) =
            __floats2bfloat162_rn(bflo(a0), bflo(a1));
        *(__nv_bfloat162*)(&g_ah[(size_t)(row0 + 8) * EMB + col]) = __floats2bfloat162_rn(b0, b1);
        *(__nv_bfloat162*)(&g_al[(size_t)(row0 + 8) * EMB + col]) =
            __floats2bfloat162_rn(bflo(b0), bflo(b1));
    }
}

// ---------------- launch ----------------
extern "C" void kernel_launch(void* const* d_in, const int* in_sizes, int n_in,
                              void* d_out, int out_size)
{
    const float* hs     = (const float*)d_in[0];
    const float* w_qkv  = (const float*)d_in[1];
    const float* b_qkv  = (const float*)d_in[2];
    const float* w_proj = (const float*)d_in[3];
    const float* b_proj = (const float*)d_in[4];
    const float* cosb   = (const float*)d_in[5];
    const float* sinb   = (const float*)d_in[6];
    const int*   cu     = (const int*)d_in[7];
    int ncu = in_sizes[7];
    float* out = (float*)d_out;

    cudaFuncSetAttribute(gemm_tc_kernel, cudaFuncAttributeMaxDynamicSharedMemorySize, GEMM_SMEM);

    __nv_bfloat16 *ah, *al, *bh, *bl;
    cudaGetSymbolAddress((void**)&ah, g_ah);
    cudaGetSymbolAddress((void**)&al, g_al);
    cudaGetSymbolAddress((void**)&bh, g_bh);
    cudaGetSymbolAddress((void**)&bl, g_bl);

    // 1) split hidden + w_qkv to bf16 hi/lo
    int nA4 = SEQ * EMB / 4, nB4 = 3 * EMB * EMB / 4;
    split_kernel<<<(nA4 + 255) / 256, 256>>>(hs, ah, al, nA4);
    split_kernel<<<(nB4 + 255) / 256, 256>>>(w_qkv, bh, bl, nB4);

    // 2) QKV GEMM (HMMA split-bf16), scatter into q/k/v
    dim3 g1(3 * EMB / 128, SEQ / 128);
    gemm_tc_kernel<<<g1, 256, GEMM_SMEM>>>(ah, al, bh, bl, b_qkv, nullptr, EMB, 0);

    // 3) RoPE
    int nrope = NH * SEQ * (HD / 2);
    rope_kernel<<<(nrope + 255) / 256, 256>>>(cosb, sinb);

    // 4) flash attention (HMMA), writes g_ah/g_al directly
    dim3 gf(SEQ / 64, NH);
    flash_kernel<<<gf, 128, FLASH_SMEM>>>(cu, ncu);

    // 5) split w_proj, then proj GEMM -> out
    int nP4 = EMB * EMB / 4;
    split_kernel<<<(nP4 + 255) / 256, 256>>>(w_proj, bh, bl, nP4);
    dim3 g2(EMB / 128, SEQ / 128);
    gemm_tc_kernel<<<g2, 256, GEMM_SMEM>>>(ah, al, bh, bl, b_proj, out, EMB, 1);
}

// round 5
// speedup vs baseline: 1.8841x; 1.8841x over previous
#include <cuda_runtime.h>
#include <cuda_bf16.h>
#include <cstdint>
#include <math.h>

#define SEQ 4096
#define EMB 1280
#define NH 16
#define HD 80
#define QKSCALE 8.94427190999915878564f  // sqrt(80) — reference MULTIPLIES by sqrt(head_dim)

// ---------------- device scratch (no allocations allowed) ----------------
__device__ float g_q[NH * SEQ * HD];
__device__ float g_k[NH * SEQ * HD];
__device__ float g_v[NH * SEQ * HD];
__device__ __align__(16) __nv_bfloat16 g_qh[NH * SEQ * HD];   // Q hi (rope+scale applied)
__device__ __align__(16) __nv_bfloat16 g_ql[NH * SEQ * HD];   // Q lo
__device__ __align__(16) __nv_bfloat16 g_kh[NH * SEQ * HD];   // K hi (rope applied)
__device__ __align__(16) __nv_bfloat16 g_kl[NH * SEQ * HD];   // K lo
__device__ __align__(16) __nv_bfloat16 g_vth[NH * HD * SEQ];  // V^T hi  [h][d][s]
__device__ __align__(16) __nv_bfloat16 g_vtl[NH * HD * SEQ];  // V^T lo
__device__ __align__(16) __nv_bfloat16 g_ah[SEQ * EMB];       // A hi (hidden / attn out)
__device__ __align__(16) __nv_bfloat16 g_al[SEQ * EMB];       // A lo
__device__ __align__(16) __nv_bfloat16 g_bh[3 * EMB * EMB];   // B hi (w_qkv / w_proj)
__device__ __align__(16) __nv_bfloat16 g_bl[3 * EMB * EMB];   // B lo

// ---------------- helpers (compute_103-safe) ----------------
__device__ __forceinline__ void mma_bf16(float* d, const uint32_t* a, const uint32_t* b) {
    asm volatile(
        "mma.sync.aligned.m16n8k16.row.col.f32.bf16.bf16.f32 "
        "{%0,%1,%2,%3}, {%4,%5,%6,%7}, {%8,%9}, {%0,%1,%2,%3};\n"
        : "+f"(d[0]), "+f"(d[1]), "+f"(d[2]), "+f"(d[3])
        : "r"(a[0]), "r"(a[1]), "r"(a[2]), "r"(a[3]), "r"(b[0]), "r"(b[1]));
}
__device__ __forceinline__ void ldm_x4(uint32_t* d, uint32_t addr) {
    asm volatile("ldmatrix.sync.aligned.m8n8.x4.shared.b16 {%0,%1,%2,%3}, [%4];"
                 : "=r"(d[0]), "=r"(d[1]), "=r"(d[2]), "=r"(d[3]) : "r"(addr));
}
__device__ __forceinline__ uint32_t smem_u32(const void* p) {
    uint32_t a;
    asm("{ .reg .u64 t; cvta.to.shared.u64 t, %1; cvt.u32.u64 %0, t; }" : "=r"(a) : "l"(p));
    return a;
}
__device__ __forceinline__ void cp_async16(uint32_t s, const void* g) {
    asm volatile("cp.async.cg.shared.global [%0], [%1], 16;\n" :: "r"(s), "l"(g));
}
#define CP_COMMIT() asm volatile("cp.async.commit_group;\n" ::: "memory")
#define CP_WAIT1()  asm volatile("cp.async.wait_group 1;\n" ::: "memory")

__device__ __forceinline__ uint32_t bf2(float x, float y) {
    __nv_bfloat162 v = __floats2bfloat162_rn(x, y);
    return *reinterpret_cast<uint32_t*>(&v);
}
__device__ __forceinline__ float bflo(float x) {
    return x - __bfloat162float(__float2bfloat16(x));
}

// ---------------- fp32 -> bf16 hi/lo split ----------------
__global__ void split_kernel(const float* __restrict__ x,
                             __nv_bfloat16* __restrict__ hi,
                             __nv_bfloat16* __restrict__ lo, int n4)
{
    int i = blockIdx.x * 256 + threadIdx.x;
    if (i >= n4) return;
    float4 v = reinterpret_cast<const float4*>(x)[i];
    __nv_bfloat16 h0 = __float2bfloat16(v.x);
    __nv_bfloat16 h1 = __float2bfloat16(v.y);
    __nv_bfloat16 h2 = __float2bfloat16(v.z);
    __nv_bfloat16 h3 = __float2bfloat16(v.w);
    __nv_bfloat162* hp = reinterpret_cast<__nv_bfloat162*>(hi);
    __nv_bfloat162* lp = reinterpret_cast<__nv_bfloat162*>(lo);
    hp[2 * i]     = __nv_bfloat162{h0, h1};
    hp[2 * i + 1] = __nv_bfloat162{h2, h3};
    lp[2 * i]     = __nv_bfloat162{__float2bfloat16(v.x - __bfloat162float(h0)),
                                   __float2bfloat16(v.y - __bfloat162float(h1))};
    lp[2 * i + 1] = __nv_bfloat162{__float2bfloat16(v.z - __bfloat162float(h2)),
                                   __float2bfloat16(v.w - __bfloat162float(h3))};
}

// ---------------- HMMA split-bf16 GEMM: C[M,N] = A*B^T + bias ----------------
#define GPAD   40
#define TILE_B (128 * GPAD * 2)
#define BUF_B  (4 * TILE_B)
#define GEMM_SMEM (2 * BUF_B)

__global__ __launch_bounds__(256, 2) void gemm_tc_kernel(
    const __nv_bfloat16* __restrict__ Ah, const __nv_bfloat16* __restrict__ Al,
    const __nv_bfloat16* __restrict__ Bh, const __nv_bfloat16* __restrict__ Bl,
    const float* __restrict__ bias, float* __restrict__ C, int K, int mode)
{
    extern __shared__ char smem[];
    uint32_t sb = smem_u32(smem);

    int t = threadIdx.x, lane = t & 31, wid = t >> 5;
    int wm = wid >> 2, wn = wid & 3;
    int c0 = blockIdx.x * 128, r0 = blockIdx.y * 128;

    const __nv_bfloat16* src[4] = {Ah + (size_t)r0 * K, Al + (size_t)r0 * K,
                                   Bh + (size_t)c0 * K, Bl + (size_t)c0 * K};

    auto load_chunk = [&](int p, int k0) {
        #pragma unroll
        for (int m = 0; m < 4; m++) {
            #pragma unroll
            for (int i = 0; i < 2; i++) {
                int e = t + i * 256;
                int row = e >> 2, col = e & 3;
                cp_async16(sb + p * BUF_B + m * TILE_B + row * (GPAD * 2) + col * 16,
                           src[m] + (size_t)row * K + k0 + col * 8);
            }
        }
    };

    float acc[4][4][4];
    #pragma unroll
    for (int a = 0; a < 4; a++)
        #pragma unroll
        for (int b = 0; b < 4; b++)
            #pragma unroll
            for (int c = 0; c < 4; c++) acc[a][b][c] = 0.f;

    int r = lane >> 2, cq = lane & 3;
    int mi = lane >> 3, mrow = lane & 7;
    int nch = K / 32;

    load_chunk(0, 0);
    CP_COMMIT();

    for (int c = 0; c < nch; c++) {
        int p = c & 1;
        if (c + 1 < nch) load_chunk(1 - p, (c + 1) * 32);
        CP_COMMIT();
        CP_WAIT1();
        __syncthreads();

        uint32_t bufu = sb + p * BUF_B;
        uint32_t tAh = bufu, tAl = bufu + TILE_B;
        uint32_t tBh = bufu + 2 * TILE_B, tBl = bufu + 3 * TILE_B;

        #pragma unroll
        for (int ks = 0; ks < 32; ks += 16) {
            uint32_t ah[4][4], al[4][4], bh[2][4], bl[2][4];
            #pragma unroll
            for (int mf = 0; mf < 4; mf++) {
                uint32_t row = wm * 64 + mf * 16 + ((mi & 1) << 3) + mrow;
                uint32_t kof = ks + ((mi >> 1) << 3);
                ldm_x4(ah[mf], tAh + row * 80 + kof * 2);
                ldm_x4(al[mf], tAl + row * 80 + kof * 2);
            }
            #pragma unroll
            for (int nfp = 0; nfp < 2; nfp++) {
                uint32_t row = wn * 32 + nfp * 16 + ((mi >> 1) << 3) + mrow;
                uint32_t kof = ks + ((mi & 1) << 3);
                ldm_x4(bh[nfp], tBh + row * 80 + kof * 2);
                ldm_x4(bl[nfp], tBl + row * 80 + kof * 2);
            }
            #pragma unroll
            for (int mf = 0; mf < 4; mf++)
                #pragma unroll
                for (int nfp = 0; nfp < 2; nfp++)
                    #pragma unroll
                    for (int j = 0; j < 2; j++) {
                        mma_bf16(acc[mf][2 * nfp + j], ah[mf], &bh[nfp][2 * j]);
                        mma_bf16(acc[mf][2 * nfp + j], ah[mf], &bl[nfp][2 * j]);
                        mma_bf16(acc[mf][2 * nfp + j], al[mf], &bh[nfp][2 * j]);
                    }
        }
        __syncthreads();
    }

    #pragma unroll
    for (int mf = 0; mf < 4; mf++) {
        #pragma unroll
        for (int nf = 0; nf < 4; nf++) {
            #pragma unroll
            for (int half = 0; half < 2; half++) {
                int row = r0 + wm * 64 + mf * 16 + r + half * 8;
                int col = c0 + wn * 32 + nf * 8 + cq * 2;
                float v0 = acc[mf][nf][half * 2 + 0] + bias[col];
                float v1 = acc[mf][nf][half * 2 + 1] + bias[col + 1];
                if (mode == 0) {
                    #pragma unroll
                    for (int j = 0; j < 2; j++) {
                        int cc = col + j;
                        float v = j ? v1 : v0;
                        int which = cc / EMB;
                        int rem = cc - which * EMB;
                        int h = rem / HD, dd = rem - h * HD;
                        float* dst = (which == 0) ? g_q : (which == 1) ? g_k : g_v;
                        dst[((size_t)h * SEQ + row) * HD + dd] = v;
                    }
                } else {
                    float2* dst = (float2*)(C + (size_t)row * EMB + col);
                    *dst = make_float2(v0, v1);
                }
            }
        }
    }
}

// ---------------- prep: RoPE + scale + hi/lo split for Q,K ----------------
__global__ void prep_qk_kernel(const float* __restrict__ cosb,
                               const float* __restrict__ sinb)
{
    int idx = blockIdx.x * blockDim.x + threadIdx.x;
    if (idx >= NH * SEQ * (HD / 2)) return;
    int d = idx % 40;
    int s = (idx / 40) % SEQ;
    int h = idx / (40 * SEQ);
    float c1 = cosb[s * HD + d],      s1 = sinb[s * HD + d];
    float c2 = cosb[s * HD + d + 40], s2 = sinb[s * HD + d + 40];
    size_t base = ((size_t)h * SEQ + s) * HD;
    float q1 = g_q[base + d], q2 = g_q[base + d + 40];
    float qa = (q1 * c1 - q2 * s1) * QKSCALE;
    float qb = (q2 * c2 + q1 * s2) * QKSCALE;
    g_qh[base + d]      = __float2bfloat16(qa);
    g_ql[base + d]      = __float2bfloat16(bflo(qa));
    g_qh[base + d + 40] = __float2bfloat16(qb);
    g_ql[base + d + 40] = __float2bfloat16(bflo(qb));
    float k1 = g_k[base + d], k2 = g_k[base + d + 40];
    float ka = k1 * c1 - k2 * s1;
    float kb = k2 * c2 + k1 * s2;
    g_kh[base + d]      = __float2bfloat16(ka);
    g_kl[base + d]      = __float2bfloat16(bflo(ka));
    g_kh[base + d + 40] = __float2bfloat16(kb);
    g_kl[base + d + 40] = __float2bfloat16(bflo(kb));
}

// ---------------- prep: V transpose + hi/lo split ----------------
__global__ void prep_v_kernel()
{
    __shared__ float vs[64 * HD];
    int t = threadIdx.x;
    int h = blockIdx.y, st0 = blockIdx.x * 64;
    const float* gv = g_v + ((size_t)h * SEQ + st0) * HD;
    #pragma unroll
    for (int i = 0; i < 20; i++) vs[t + i * 256] = gv[t + i * 256];
    __syncthreads();
    #pragma unroll
    for (int i = 0; i < 20; i++) {
        int e = t + i * 256;
        int d = e >> 6, s = e & 63;
        float v = vs[s * HD + d];
        size_t o = ((size_t)h * HD + d) * SEQ + st0 + s;
        g_vth[o] = __float2bfloat16(v);
        g_vtl[o] = __float2bfloat16(bflo(v));
    }
}

// ---------------- Flash attention, HMMA split-bf16, double-buffered ----------------
// per-stage smem: Kh 64x88 (11264B), Kl 11264, Vh 80x72 (11520B), Vl 11520 = 45568
#define KROW 88
#define VROW 72
#define FSTAGE 45568
#define FLASH_SMEM (2 * FSTAGE)   // 91136

__global__ __launch_bounds__(128) void flash_kernel(const int* __restrict__ cu, int ncu)
{
    extern __shared__ char fsm[];
    uint32_t sb = smem_u32(fsm);

    int t = threadIdx.x, lane = t & 31, wid = t >> 5;
    int r = lane >> 2, cq = lane & 3;
    int mi = lane >> 3, mrow = lane & 7;
    int h = blockIdx.y, qr0 = blockIdx.x * 64;

    // ---- Q fragments (hi/lo) from prepped global ----
    uint32_t qh[5][4], ql[5][4];
    {
        const __nv_bfloat16* qsh = g_qh + ((size_t)h * SEQ + qr0 + wid * 16) * HD;
        const __nv_bfloat16* qsl = g_ql + ((size_t)h * SEQ + qr0 + wid * 16) * HD;
        #pragma unroll
        for (int ks = 0; ks < 5; ks++) {
            #pragma unroll
            for (int idx = 0; idx < 4; idx++) {
                int row = r + (idx & 1) * 8;
                int k = ks * 16 + 2 * cq + (idx >> 1) * 8;
                qh[ks][idx] = *(const uint32_t*)(qsh + row * HD + k);
                ql[ks][idx] = *(const uint32_t*)(qsl + row * HD + k);
            }
        }
    }

    int s0 = 0, s1 = SEQ;
    for (int i = 0; i < ncu - 1; i++) {
        if (cu[i] <= qr0 && qr0 < cu[i + 1]) { s0 = cu[i]; s1 = cu[i + 1]; break; }
    }

    const __nv_bfloat16* kbh = g_kh + (size_t)h * SEQ * HD;
    const __nv_bfloat16* kbl = g_kl + (size_t)h * SEQ * HD;
    const __nv_bfloat16* vbh = g_vth + (size_t)h * HD * SEQ;
    const __nv_bfloat16* vbl = g_vtl + (size_t)h * HD * SEQ;

    auto load_kv = [&](int p, int kt) {
        uint32_t base = sb + p * FSTAGE;
        #pragma unroll
        for (int i = 0; i < 5; i++) {
            int e = t + i * 128;
            int row = e / 10, c = e - row * 10;
            cp_async16(base + row * 176 + c * 16, kbh + ((size_t)(kt + row)) * HD + c * 8);
            cp_async16(base + 11264 + row * 176 + c * 16, kbl + ((size_t)(kt + row)) * HD + c * 8);
        }
        #pragma unroll
        for (int i = 0; i < 5; i++) {
            int e = t + i * 128;
            int d = e >> 3, c = e & 7;
            cp_async16(base + 22528 + d * 144 + c * 16, vbh + (size_t)d * SEQ + kt + c * 8);
            cp_async16(base + 34048 + d * 144 + c * 16, vbl + (size_t)d * SEQ + kt + c * 8);
        }
    };

    float o[10][4];
    #pragma unroll
    for (int nf = 0; nf < 10; nf++)
        #pragma unroll
        for (int j = 0; j < 4; j++) o[nf][j] = 0.f;
    float m0 = -INFINITY, m1 = -INFINITY, l0 = 0.f, l1 = 0.f;

    int nt = (s1 - s0) >> 6;
    load_kv(0, s0);
    CP_COMMIT();

    for (int it = 0; it < nt; it++) {
        int p = it & 1;
        if (it + 1 < nt) load_kv(1 - p, s0 + (it + 1) * 64);
        CP_COMMIT();
        CP_WAIT1();
        __syncthreads();

        uint32_t kbase = sb + p * FSTAGE;
        uint32_t vbase = kbase + 22528;

        // ---- S = Q K^T (3-term split) ----
        float s[8][4];
        #pragma unroll
        for (int nf = 0; nf < 8; nf++)
            #pragma unroll
            for (int j = 0; j < 4; j++) s[nf][j] = 0.f;

        #pragma unroll
        for (int ks = 0; ks < 5; ks++) {
            #pragma unroll
            for (int nfp = 0; nfp < 4; nfp++) {
                uint32_t nrow = nfp * 16 + ((mi >> 1) << 3) + mrow;
                uint32_t kof = ks * 16 + ((mi & 1) << 3);
                uint32_t a = kbase + nrow * 176 + kof * 2;
                uint32_t bh4[4], bl4[4];
                ldm_x4(bh4, a);
                ldm_x4(bl4, a + 11264);
                mma_bf16(s[2 * nfp],     qh[ks], &bh4[0]);
                mma_bf16(s[2 * nfp + 1], qh[ks], &bh4[2]);
                mma_bf16(s[2 * nfp],     qh[ks], &bl4[0]);
                mma_bf16(s[2 * nfp + 1], qh[ks], &bl4[2]);
                mma_bf16(s[2 * nfp],     ql[ks], &bh4[0]);
                mma_bf16(s[2 * nfp + 1], ql[ks], &bh4[2]);
            }
        }

        // ---- online softmax (rows r, r+8; quad reduction) ----
        float mx0 = -INFINITY, mx1 = -INFINITY;
        #pragma unroll
        for (int nf = 0; nf < 8; nf++) {
            mx0 = fmaxf(mx0, fmaxf(s[nf][0], s[nf][1]));
            mx1 = fmaxf(mx1, fmaxf(s[nf][2], s[nf][3]));
        }
        mx0 = fmaxf(mx0, __shfl_xor_sync(0xffffffffu, mx0, 1));
        mx0 = fmaxf(mx0, __shfl_xor_sync(0xffffffffu, mx0, 2));
        mx1 = fmaxf(mx1, __shfl_xor_sync(0xffffffffu, mx1, 1));
        mx1 = fmaxf(mx1, __shfl_xor_sync(0xffffffffu, mx1, 2));
        float mn0 = fmaxf(m0, mx0), mn1 = fmaxf(m1, mx1);
        float c0 = __expf(m0 - mn0), c1 = __expf(m1 - mn1);
        float sum0 = 0.f, sum1 = 0.f;
        #pragma unroll
        for (int nf = 0; nf < 8; nf++) {
            s[nf][0] = __expf(s[nf][0] - mn0); sum0 += s[nf][0];
            s[nf][1] = __expf(s[nf][1] - mn0); sum0 += s[nf][1];
            s[nf][2] = __expf(s[nf][2] - mn1); sum1 += s[nf][2];
            s[nf][3] = __expf(s[nf][3] - mn1); sum1 += s[nf][3];
        }
        sum0 += __shfl_xor_sync(0xffffffffu, sum0, 1);
        sum0 += __shfl_xor_sync(0xffffffffu, sum0, 2);
        sum1 += __shfl_xor_sync(0xffffffffu, sum1, 1);
        sum1 += __shfl_xor_sync(0xffffffffu, sum1, 2);
        l0 = l0 * c0 + sum0; l1 = l1 * c1 + sum1;
        m0 = mn0; m1 = mn1;
        #pragma unroll
        for (int nf = 0; nf < 10; nf++) {
            o[nf][0] *= c0; o[nf][1] *= c0;
            o[nf][2] *= c1; o[nf][3] *= c1;
        }

        // ---- pack P into A-operand fragments (hi/lo) ----
        uint32_t ph[4][4], pl[4][4];
        #pragma unroll
        for (int kf = 0; kf < 4; kf++) {
            float* j0 = s[2 * kf];
            float* j1 = s[2 * kf + 1];
            ph[kf][0] = bf2(j0[0], j0[1]); pl[kf][0] = bf2(bflo(j0[0]), bflo(j0[1]));
            ph[kf][1] = bf2(j0[2], j0[3]); pl[kf][1] = bf2(bflo(j0[2]), bflo(j0[3]));
            ph[kf][2] = bf2(j1[0], j1[1]); pl[kf][2] = bf2(bflo(j1[0]), bflo(j1[1]));
            ph[kf][3] = bf2(j1[2], j1[3]); pl[kf][3] = bf2(bflo(j1[2]), bflo(j1[3]));
        }

        // ---- O += P V (3-term split) ----
        #pragma unroll
        for (int kf = 0; kf < 4; kf++) {
            #pragma unroll
            for (int nfp = 0; nfp < 5; nfp++) {
                uint32_t nrow = nfp * 16 + ((mi >> 1) << 3) + mrow;
                uint32_t kof = kf * 16 + ((mi & 1) << 3);
                uint32_t a = vbase + nrow * 144 + kof * 2;
                uint32_t vh4[4], vl4[4];
                ldm_x4(vh4, a);
                ldm_x4(vl4, a + 11520);
                mma_bf16(o[2 * nfp],     ph[kf], &vh4[0]);
                mma_bf16(o[2 * nfp + 1], ph[kf], &vh4[2]);
                mma_bf16(o[2 * nfp],     ph[kf], &vl4[0]);
                mma_bf16(o[2 * nfp + 1], ph[kf], &vl4[2]);
                mma_bf16(o[2 * nfp],     pl[kf], &vh4[0]);
                mma_bf16(o[2 * nfp + 1], pl[kf], &vh4[2]);
            }
        }
        __syncthreads();
    }

    // ---- epilogue: normalize, split hi/lo, write to g_ah/g_al ----
    float inv0 = 1.f / l0, inv1 = 1.f / l1;
    int row0 = qr0 + wid * 16 + r;
    #pragma unroll
    for (int nf = 0; nf < 10; nf++) {
        int col = h * HD + nf * 8 + 2 * cq;
        float a0 = o[nf][0] * inv0, a1 = o[nf][1] * inv0;
        float b0 = o[nf][2] * inv1, b1 = o[nf][3] * inv1;
        *(__nv_bfloat162*)(&g_ah[(size_t)row0 * EMB + col]) = __floats2bfloat162_rn(a0, a1);
        *(__nv_bfloat162*)(&g_al[(size_t)row0 * EMB + col]) =
            __floats2bfloat162_rn(bflo(a0), bflo(a1));
        *(__nv_bfloat162*)(&g_ah[(size_t)(row0 + 8) * EMB + col]) = __floats2bfloat162_rn(b0, b1);
        *(__nv_bfloat162*)(&g_al[(size_t)(row0 + 8) * EMB + col]) =
            __floats2bfloat162_rn(bflo(b0), bflo(b1));
    }
}

// ---------------- launch ----------------
extern "C" void kernel_launch(void* const* d_in, const int* in_sizes, int n_in,
                              void* d_out, int out_size)
{
    const float* hs     = (const float*)d_in[0];
    const float* w_qkv  = (const float*)d_in[1];
    const float* b_qkv  = (const float*)d_in[2];
    const float* w_proj = (const float*)d_in[3];
    const float* b_proj = (const float*)d_in[4];
    const float* cosb   = (const float*)d_in[5];
    const float* sinb   = (const float*)d_in[6];
    const int*   cu     = (const int*)d_in[7];
    int ncu = in_sizes[7];
    float* out = (float*)d_out;

    cudaFuncSetAttribute(gemm_tc_kernel, cudaFuncAttributeMaxDynamicSharedMemorySize, GEMM_SMEM);
    cudaFuncSetAttribute(flash_kernel, cudaFuncAttributeMaxDynamicSharedMemorySize, FLASH_SMEM);

    __nv_bfloat16 *ah, *al, *bh, *bl;
    cudaGetSymbolAddress((void**)&ah, g_ah);
    cudaGetSymbolAddress((void**)&al, g_al);
    cudaGetSymbolAddress((void**)&bh, g_bh);
    cudaGetSymbolAddress((void**)&bl, g_bl);

    // 1) split hidden + w_qkv to bf16 hi/lo
    int nA4 = SEQ * EMB / 4, nB4 = 3 * EMB * EMB / 4;
    split_kernel<<<(nA4 + 255) / 256, 256>>>(hs, ah, al, nA4);
    split_kernel<<<(nB4 + 255) / 256, 256>>>(w_qkv, bh, bl, nB4);

    // 2) QKV GEMM (HMMA split-bf16), scatter into q/k/v fp32
    dim3 g1(3 * EMB / 128, SEQ / 128);
    gemm_tc_kernel<<<g1, 256, GEMM_SMEM>>>(ah, al, bh, bl, b_qkv, nullptr, EMB, 0);

    // 3) prep: RoPE+scale+split Q,K ; transpose+split V
    int nrope = NH * SEQ * (HD / 2);
    prep_qk_kernel<<<(nrope + 255) / 256, 256>>>(cosb, sinb);
    dim3 gv(SEQ / 64, NH);
    prep_v_kernel<<<gv, 256>>>();

    // 4) flash attention (HMMA, cp.async double-buffered), writes g_ah/g_al
    dim3 gf(SEQ / 64, NH);
    flash_kernel<<<gf, 128, FLASH_SMEM>>>(cu, ncu);

    // 5) split w_proj, then proj GEMM -> out
    int nP4 = EMB * EMB / 4;
    split_kernel<<<(nP4 + 255) / 256, 256>>>(w_proj, bh, bl, nP4);
    dim3 g2(EMB / 128, SEQ / 128);
    gemm_tc_kernel<<<g2, 256, GEMM_SMEM>>>(ah, al, bh, bl, b_proj, out, EMB, 1);
}